// round 1
// baseline (speedup 1.0000x reference)
#include <cuda_runtime.h>
#include <math.h>

#define BB   256
#define LL   196
#define RR   100
#define RNN  1024
#define ATTHD 512
#define NSUM 6144
#define MINV -100000000.0f

// ---------------- scratch (no allocation allowed) ----------------
__device__ float g_atth1[BB * ATTHD];
__device__ float g_atth2[BB * ATTHD];
__device__ float g_res1[BB * RNN];
__device__ float g_res2[BB * RNN];
__device__ float g_sums[BB * NSUM];
__device__ float g_a2c[BB * 2 * RNN];
__device__ float g_fakebox[BB * RNN];
__device__ float g_fakereg[BB * RNN];
__device__ float g_fre[BB * ATTHD];
__device__ float g_hoe[BB * ATTHD];
__device__ int   g_mask_is_byte;

// ---------------- mask dtype detection ----------------
// bool/u8 mask: bytes in {0,1} -> some 32-bit word has nonzero bytes above byte0.
// int32 mask:   words in {0,1} -> upper bytes always 0.
// float32 mask: words in {0, 0x3F800000}; 0x3F800000 is excluded explicitly.
__global__ void detect_mask_kernel(const unsigned int* __restrict__ w, int nwords) {
    __shared__ int s;
    if (threadIdx.x == 0) s = 0;
    __syncthreads();
    int found = 0;
    for (int i = threadIdx.x; i < nwords; i += blockDim.x) {
        unsigned v = w[i];
        if ((v & 0xFFFFFF00u) != 0u && v != 0x3F800000u) found = 1;
    }
    if (found) atomicOr(&s, 1);
    __syncthreads();
    if (threadIdx.x == 0) g_mask_is_byte = s;
}

__device__ __forceinline__ bool mask_at(const void* p, long i) {
    if (g_mask_is_byte) return ((const unsigned char*)p)[i] != 0;
    return ((const unsigned int*)p)[i] != 0u;  // works for int32 and float32 (1.0f != 0)
}

// ---------------- generic tiled GEMM ----------------
// C[M,N] = act( sum_pairs A_p @ W_p + bias0 + bias1 )
// A row-major MxK, W row-major KxN. BM=BN=64, BK=16, 256 threads, 4x4 per thread.
#define GBM 64
#define GBN 64
#define GBK 16

template<int NPAIR, int ACT>
__global__ __launch_bounds__(256)
void gemm_kernel(const float* __restrict__ A0, const float* __restrict__ W0,
                 const float* __restrict__ A1, const float* __restrict__ W1,
                 const float* __restrict__ b0, const float* __restrict__ b1,
                 float* __restrict__ C, int M, int N, int K) {
    __shared__ float As[GBK][GBM + 4];
    __shared__ float Bs[GBK][GBN + 4];

    const int bm = blockIdx.y * GBM;
    const int bn = blockIdx.x * GBN;
    const int tid = threadIdx.x;
    const int tr = tid / 16;          // 0..15
    const int tc = tid % 16;          // 0..15

    // A tile load mapping: 64 rows x 16 cols, one float4 per thread
    const int arow = tid >> 2;             // 0..63
    const int acol4 = (tid & 3) * 4;       // 0,4,8,12
    // B tile: 16 rows x 64 cols
    const int brow = tid >> 4;             // 0..15
    const int bcol4 = (tid & 15) * 4;      // 0..60

    float acc[4][4] = {};

    for (int pair = 0; pair < NPAIR; ++pair) {
        const float* A = (pair == 0) ? A0 : A1;
        const float* W = (pair == 0) ? W0 : W1;
        for (int k0 = 0; k0 < K; k0 += GBK) {
            float4 av = *(const float4*)(A + (long)(bm + arow) * K + k0 + acol4);
            float4 bv = *(const float4*)(W + (long)(k0 + brow) * N + bn + bcol4);
            __syncthreads();
            As[acol4 + 0][arow] = av.x;
            As[acol4 + 1][arow] = av.y;
            As[acol4 + 2][arow] = av.z;
            As[acol4 + 3][arow] = av.w;
            *(float4*)&Bs[brow][bcol4] = bv;
            __syncthreads();
#pragma unroll
            for (int k = 0; k < GBK; ++k) {
                float a[4], b[4];
                *(float4*)a = *(const float4*)&As[k][tr * 4];
                *(float4*)b = *(const float4*)&Bs[k][tc * 4];
#pragma unroll
                for (int i = 0; i < 4; ++i)
#pragma unroll
                    for (int j = 0; j < 4; ++j)
                        acc[i][j] += a[i] * b[j];
            }
        }
    }

    float bias[4];
#pragma unroll
    for (int j = 0; j < 4; ++j) {
        int n = bn + tc * 4 + j;
        float bv = b0 ? b0[n] : 0.0f;
        if (b1) bv += b1[n];
        bias[j] = bv;
    }
#pragma unroll
    for (int i = 0; i < 4; ++i) {
        int m = bm + tr * 4 + i;
#pragma unroll
        for (int j = 0; j < 4; ++j) {
            float v = acc[i][j] + bias[j];
            if (ACT == 1) v = fmaxf(v, 0.0f);
            C[(long)m * N + bn + tc * 4 + j] = v;
        }
    }
}

// ---------------- fused additive attention ----------------
// One block per batch row b. 512 threads (= ATTHD) = 16 warps.
// score[n] = sum_k tanh(p[b,n,k] + atth[b,k]) * Wa[k] + ba; mask; softmax; out = w @ feats
__global__ __launch_bounds__(512)
void attention_kernel(const float* __restrict__ p_feats,  // B x N x ATTHD
                      const float* __restrict__ feats,    // B x N x RNN
                      const float* __restrict__ atth,     // B x ATTHD
                      const float* __restrict__ Wa,       // ATTHD
                      const float* __restrict__ ba,       // scalar
                      const void*  __restrict__ mask,     // B x (RR+1), use col 1+n; may be null
                      int N,
                      float* __restrict__ out)            // B x RNN
{
    const int b = blockIdx.x;
    const int tid = threadIdx.x;
    const int lane = tid & 31, warp = tid >> 5;

    __shared__ float sh_h[ATTHD];
    __shared__ float sh_w[ATTHD];
    __shared__ float sc[224];
    __shared__ float red[16];

    sh_h[tid] = atth[(long)b * ATTHD + tid];
    sh_w[tid] = Wa[tid];
    __syncthreads();

    const float bav = ba[0];

    for (int l = warp; l < N; l += 16) {
        const float* row = p_feats + ((long)b * N + l) * ATTHD;
        float part = 0.0f;
#pragma unroll
        for (int j = 0; j < 16; ++j) {
            int k = lane + 32 * j;
            part += tanhf(row[k] + sh_h[k]) * sh_w[k];
        }
#pragma unroll
        for (int o = 16; o; o >>= 1) part += __shfl_xor_sync(0xffffffffu, part, o);
        if (lane == 0) {
            float s = part + bav;
            if (mask != nullptr && mask_at(mask, (long)b * (RR + 1) + 1 + l)) s = MINV;
            sc[l] = s;
        }
    }
    __syncthreads();

    // softmax over sc[0..N)
    float v = (tid < N) ? sc[tid] : -3.0e38f;
    float m = v;
#pragma unroll
    for (int o = 16; o; o >>= 1) m = fmaxf(m, __shfl_xor_sync(0xffffffffu, m, o));
    if (lane == 0) red[warp] = m;
    __syncthreads();
    if (warp == 0) {
        float t = (lane < 16) ? red[lane] : -3.0e38f;
#pragma unroll
        for (int o = 16; o; o >>= 1) t = fmaxf(t, __shfl_xor_sync(0xffffffffu, t, o));
        if (lane == 0) red[0] = t;
    }
    __syncthreads();
    const float smax = red[0];
    __syncthreads();

    float e = (tid < N) ? expf(v - smax) : 0.0f;
    float ssum = e;
#pragma unroll
    for (int o = 16; o; o >>= 1) ssum += __shfl_xor_sync(0xffffffffu, ssum, o);
    if (lane == 0) red[warp] = ssum;
    __syncthreads();
    if (warp == 0) {
        float t = (lane < 16) ? red[lane] : 0.0f;
#pragma unroll
        for (int o = 16; o; o >>= 1) t += __shfl_xor_sync(0xffffffffu, t, o);
        if (lane == 0) red[0] = t;
    }
    __syncthreads();
    const float inv = 1.0f / red[0];
    if (tid < N) sc[tid] = e * inv;
    __syncthreads();

    // out[b, :] = sum_l sc[l] * feats[b, l, :]   (thread -> 2 consecutive dims)
    const float2* f2 = (const float2*)(feats + (long)b * N * RNN);
    float ax = 0.0f, ay = 0.0f;
#pragma unroll 4
    for (int l = 0; l < N; ++l) {
        float w = sc[l];
        float2 vv = f2[(long)l * (RNN / 2) + tid];
        ax += w * vv.x;
        ay += w * vv.y;
    }
    ((float2*)(out + (long)b * RNN))[tid] = make_float2(ax, ay);
}

// ---------------- LSTM elementwise ----------------
__global__ __launch_bounds__(256)
void lstm_kernel(const float* __restrict__ sums, const float* __restrict__ a2c,
                 const float* __restrict__ cprev,
                 float* __restrict__ outp, float* __restrict__ outh,
                 float* __restrict__ outc, float* __restrict__ fb) {
    int i = blockIdx.x * blockDim.x + threadIdx.x;
    if (i >= BB * RNN) return;
    int b = i >> 10, d = i & 1023;
    const float* s = sums + (long)b * NSUM;
    float ig = 1.0f / (1.0f + expf(-s[d]));
    float fg = 1.0f / (1.0f + expf(-s[RNN + d]));
    float og = 1.0f / (1.0f + expf(-s[2 * RNN + d]));
    float sg = 1.0f / (1.0f + expf(-s[3 * RNN + d]));
    float t1 = s[4 * RNN + d] + a2c[(long)b * 2 * RNN + d];
    float t2 = s[5 * RNN + d] + a2c[(long)b * 2 * RNN + RNN + d];
    float intr = fmaxf(t1, t2);
    float c = fg * cprev[i] + ig * intr;
    float tc = tanhf(c);
    float h = og * tc;
    outp[i] = h;
    outh[i] = h;
    outc[i] = c;
    fb[i] = sg * tc;
}

// ---------------- det_prob ----------------
// det[b,n] = tanh( (n==0 ? fre[b,:] : p_pool[b,n-1,:]) + hoe[b,:] ) . Wp + bp ; masked
__global__ __launch_bounds__(512)
void det_kernel(const float* __restrict__ fre, const float* __restrict__ hoe,
                const float* __restrict__ p_pool, const float* __restrict__ Wp,
                const float* __restrict__ bp, const void* __restrict__ pnt,
                float* __restrict__ det) {
    const int b = blockIdx.x;
    const int tid = threadIdx.x;
    const int lane = tid & 31, warp = tid >> 5;
    __shared__ float sh_h[ATTHD], sh_w[ATTHD], sh_f[ATTHD];
    sh_h[tid] = hoe[(long)b * ATTHD + tid];
    sh_w[tid] = Wp[tid];
    sh_f[tid] = fre[(long)b * ATTHD + tid];
    __syncthreads();
    const float bpv = bp[0];
    for (int n = warp; n < RR + 1; n += 16) {
        float part = 0.0f;
        if (n == 0) {
#pragma unroll
            for (int j = 0; j < 16; ++j) {
                int k = lane + 32 * j;
                part += tanhf(sh_f[k] + sh_h[k]) * sh_w[k];
            }
        } else {
            const float* row = p_pool + ((long)b * RR + (n - 1)) * ATTHD;
#pragma unroll
            for (int j = 0; j < 16; ++j) {
                int k = lane + 32 * j;
                part += tanhf(row[k] + sh_h[k]) * sh_w[k];
            }
        }
#pragma unroll
        for (int o = 16; o; o >>= 1) part += __shfl_xor_sync(0xffffffffu, part, o);
        if (lane == 0) {
            float s = part + bpv;
            if (mask_at(pnt, (long)b * (RR + 1) + n)) s = MINV;
            det[(long)b * (RR + 1) + n] = s;
        }
    }
}

// ---------------- host launch ----------------
extern "C" void kernel_launch(void* const* d_in, const int* in_sizes, int n_in,
                              void* d_out, int out_size) {
    // input order (metadata): 0 xt, 1 fc_feats, 2 att_feats, 3 p_att_feats,
    // 4 pool_feats, 5 p_pool_feats, 6 att_mask, 7 pnt_mask, 8 state_h, 9 state_c,
    // 10 W_h2att, 11 b_h2att, 12 W_alpha1, 13 b_alpha1, 14 W_h1att, 15 b_h1att,
    // 16 W_alpha2, 17 b_alpha2, 18 W_i2h, 19 b_i2h, 20 W_h2h, 21 b_h2h,
    // 22 W_a2c1, 23 b_a2c1, 24 W_ffc1, 25 b_ffc1, 26 W_ffc2, 27 b_ffc2,
    // 28 W_hfc1, 29 b_hfc1, 30 W_alphap, 31 b_alphap
    const float* xt        = (const float*)d_in[0];
    const float* att_feats = (const float*)d_in[2];
    const float* p_att     = (const float*)d_in[3];
    const float* pool_f    = (const float*)d_in[4];
    const float* p_pool    = (const float*)d_in[5];
    const void*  att_mask  = d_in[6];
    const void*  pnt_mask  = d_in[7];
    const float* h_prev    = (const float*)d_in[8];
    const float* c_prev    = (const float*)d_in[9];
    const float* W_h2att = (const float*)d_in[10]; const float* b_h2att = (const float*)d_in[11];
    const float* W_a1    = (const float*)d_in[12]; const float* b_a1    = (const float*)d_in[13];
    const float* W_h1att = (const float*)d_in[14]; const float* b_h1att = (const float*)d_in[15];
    const float* W_a2    = (const float*)d_in[16]; const float* b_a2    = (const float*)d_in[17];
    const float* W_i2h   = (const float*)d_in[18]; const float* b_i2h   = (const float*)d_in[19];
    const float* W_h2h   = (const float*)d_in[20]; const float* b_h2h   = (const float*)d_in[21];
    const float* W_a2c1  = (const float*)d_in[22]; const float* b_a2c1  = (const float*)d_in[23];
    const float* W_ffc1  = (const float*)d_in[24]; const float* b_ffc1  = (const float*)d_in[25];
    const float* W_ffc2  = (const float*)d_in[26]; const float* b_ffc2  = (const float*)d_in[27];
    const float* W_hfc1  = (const float*)d_in[28]; const float* b_hfc1  = (const float*)d_in[29];
    const float* W_ap    = (const float*)d_in[30]; const float* b_ap    = (const float*)d_in[31];

    float* out = (float*)d_out;
    float* out_output = out;                                   // B*RNN
    float* out_det    = out + (long)BB * RNN;                  // B*(RR+1)
    float* out_h      = out_det + (long)BB * (RR + 1);         // B*RNN
    float* out_c      = out_h + (long)BB * RNN;                // B*RNN

    float *atth1, *atth2, *res1, *res2, *sums, *a2c, *fakebox, *fakereg, *fre, *hoe;
    cudaGetSymbolAddress((void**)&atth1,   g_atth1);
    cudaGetSymbolAddress((void**)&atth2,   g_atth2);
    cudaGetSymbolAddress((void**)&res1,    g_res1);
    cudaGetSymbolAddress((void**)&res2,    g_res2);
    cudaGetSymbolAddress((void**)&sums,    g_sums);
    cudaGetSymbolAddress((void**)&a2c,     g_a2c);
    cudaGetSymbolAddress((void**)&fakebox, g_fakebox);
    cudaGetSymbolAddress((void**)&fakereg, g_fakereg);
    cudaGetSymbolAddress((void**)&fre,     g_fre);
    cudaGetSymbolAddress((void**)&hoe,     g_hoe);

    const int K = RNN;  // all GEMMs have K=1024
    dim3 blk(256);

    // 0. mask dtype detection (att_mask and pnt_mask share dtype)
    detect_mask_kernel<<<1, 256>>>((const unsigned int*)att_mask, BB * (RR + 1) / 4);

    // 1. atth1 = h @ W_h2att + b ; atth2 = h @ W_h1att + b
    {
        dim3 g(ATTHD / GBN, BB / GBM);
        gemm_kernel<1, 0><<<g, blk>>>(h_prev, W_h2att, nullptr, nullptr, b_h2att, nullptr,
                                      atth1, BB, ATTHD, K);
        gemm_kernel<1, 0><<<g, blk>>>(h_prev, W_h1att, nullptr, nullptr, b_h1att, nullptr,
                                      atth2, BB, ATTHD, K);
    }

    // 2. fused attentions
    attention_kernel<<<BB, 512>>>(p_att, att_feats, atth1, W_a1, b_a1, nullptr, LL, res1);
    attention_kernel<<<BB, 512>>>(p_pool, pool_f, atth2, W_a2, b_a2, att_mask, RR, res2);

    // 3. sums = xt @ W_i2h + h @ W_h2h + b_i2h + b_h2h
    {
        dim3 g(NSUM / GBN, BB / GBM);
        gemm_kernel<2, 0><<<g, blk>>>(xt, W_i2h, h_prev, W_h2h, b_i2h, b_h2h,
                                      sums, BB, NSUM, K);
    }

    // 4. a2c = (res1 + res2) @ W_a2c1 + 2*b_a2c1
    {
        dim3 g(2 * RNN / GBN, BB / GBM);
        gemm_kernel<2, 0><<<g, blk>>>(res1, W_a2c1, res2, W_a2c1, b_a2c1, b_a2c1,
                                      a2c, BB, 2 * RNN, K);
    }

    // 5. LSTM elementwise -> output, next_h, next_c, fake_box
    lstm_kernel<<<(BB * RNN + 255) / 256, 256>>>(sums, a2c, c_prev,
                                                 out_output, out_h, out_c, fakebox);

    // 6. fake_region = relu(fake_box @ W_ffc1 + b)
    {
        dim3 g(RNN / GBN, BB / GBM);
        gemm_kernel<1, 1><<<g, blk>>>(fakebox, W_ffc1, nullptr, nullptr, b_ffc1, nullptr,
                                      fakereg, BB, RNN, K);
    }
    // 7. fre = fake_region @ W_ffc2 + b ; hoe = next_h @ W_hfc1 + b
    {
        dim3 g(ATTHD / GBN, BB / GBM);
        gemm_kernel<1, 0><<<g, blk>>>(fakereg, W_ffc2, nullptr, nullptr, b_ffc2, nullptr,
                                      fre, BB, ATTHD, K);
        gemm_kernel<1, 0><<<g, blk>>>(out_h, W_hfc1, nullptr, nullptr, b_hfc1, nullptr,
                                      hoe, BB, ATTHD, K);
    }

    // 8. det_prob
    det_kernel<<<BB, 512>>>(fre, hoe, p_pool, W_ap, b_ap, pnt_mask, out_det);

    (void)in_sizes; (void)n_in; (void)out_size;
}

// round 3
// speedup vs baseline: 2.2994x; 2.2994x over previous
#include <cuda_runtime.h>
#include <math.h>

#define BB   256
#define LL   196
#define RR   100
#define RNN  1024
#define ATTHD 512
#define NSUM 6144
#define MINV -100000000.0f

// ---------------- scratch (no allocation allowed; 16B-aligned for float4 access) ----------------
__device__ __align__(16) float g_atth1[BB * ATTHD];
__device__ __align__(16) float g_atth2[BB * ATTHD];
__device__ __align__(16) float g_res1[BB * RNN];
__device__ __align__(16) float g_res2[BB * RNN];
__device__ __align__(16) float g_sums[BB * NSUM];
__device__ __align__(16) float g_a2c[BB * 2 * RNN];
__device__ __align__(16) float g_fakebox[BB * RNN];
__device__ __align__(16) float g_fakereg[BB * RNN];
__device__ __align__(16) float g_fre[BB * ATTHD];
__device__ __align__(16) float g_hoe[BB * ATTHD];
__device__ __align__(16) float g_w1[BB * 224];
__device__ __align__(16) float g_w2[BB * 224];
__device__ int   g_mask_is_byte;

// ---------------- mask dtype detection ----------------
__global__ void detect_mask_kernel(const unsigned int* __restrict__ w, int nwords) {
    __shared__ int s;
    if (threadIdx.x == 0) s = 0;
    __syncthreads();
    int found = 0;
    for (int i = threadIdx.x; i < nwords; i += blockDim.x) {
        unsigned v = w[i];
        if ((v & 0xFFFFFF00u) != 0u && v != 0x3F800000u) found = 1;
    }
    if (found) atomicOr(&s, 1);
    __syncthreads();
    if (threadIdx.x == 0) g_mask_is_byte = s;
}

__device__ __forceinline__ bool mask_at(const void* p, long i) {
    if (g_mask_is_byte) return ((const unsigned char*)p)[i] != 0;
    return ((const unsigned int*)p)[i] != 0u;
}

// ---------------- TF32 tensor-core GEMM ----------------
// C[M,N] = act( sum_pairs A_p @ W_p + b0 + b1 ), K fixed at 1024.
// 128 threads, block tile 64x64, BK=32, warps 2x2 each 32x32 via m16n8k8.
// blockIdx.z==1 selects the alternate (A0b,W0b,b0b,Cb) single-pair problem.

__device__ __forceinline__ unsigned f2t(float x) {
    unsigned r;
    asm("cvt.rna.tf32.f32 %0, %1;" : "=r"(r) : "f"(x));
    return r;
}

template<int NPAIR, int ACT>
__global__ __launch_bounds__(128, 4)
void mma_gemm(const float* __restrict__ A0, const float* __restrict__ W0,
              const float* __restrict__ A1, const float* __restrict__ W1,
              const float* __restrict__ b0, const float* __restrict__ b1,
              float* __restrict__ C,
              const float* __restrict__ A0b, const float* __restrict__ W0b,
              const float* __restrict__ b0b, float* __restrict__ Cb,
              int M, int N) {
    if (blockIdx.z == 1) { A0 = A0b; W0 = W0b; b0 = b0b; C = Cb; }
    constexpr int K = 1024;
    constexpr int K32 = K / 32;
    constexpr int ITER = NPAIR * K32;

    __shared__ unsigned As[64][36];   // [m][k]
    __shared__ unsigned Bs[32][72];   // [k][n]

    const int tid = threadIdx.x;
    const int lane = tid & 31, warp = tid >> 5;
    const int gid = lane >> 2, tg = lane & 3;
    const int wm = (warp >> 1) * 32, wn = (warp & 1) * 32;
    const int bm = blockIdx.y * 64, bn = blockIdx.x * 64;

    const int rowA = tid >> 3;          // +16*i
    const int colA = (tid & 7) * 4;
    const int rowB = tid >> 4;          // +8*i
    const int colB = (tid & 15) * 4;

    float4 pa[4], pb[4];
    float c[2][4][4] = {};

    auto gload = [&](int it) {
        const float* A = (it < K32) ? A0 : A1;
        const float* W = (it < K32) ? W0 : W1;
        const int k0 = (it & (K32 - 1)) * 32;
#pragma unroll
        for (int i = 0; i < 4; ++i)
            pa[i] = *(const float4*)(A + (long)(bm + rowA + 16 * i) * K + k0 + colA);
#pragma unroll
        for (int i = 0; i < 4; ++i)
            pb[i] = *(const float4*)(W + (long)(k0 + rowB + 8 * i) * N + bn + colB);
    };
    auto sstore = [&]() {
#pragma unroll
        for (int i = 0; i < 4; ++i) {
            uint4 v = make_uint4(f2t(pa[i].x), f2t(pa[i].y), f2t(pa[i].z), f2t(pa[i].w));
            *(uint4*)&As[rowA + 16 * i][colA] = v;
        }
#pragma unroll
        for (int i = 0; i < 4; ++i) {
            uint4 v = make_uint4(f2t(pb[i].x), f2t(pb[i].y), f2t(pb[i].z), f2t(pb[i].w));
            *(uint4*)&Bs[rowB + 8 * i][colB] = v;
        }
    };
    auto compute = [&]() {
#pragma unroll
        for (int kk = 0; kk < 4; ++kk) {
            unsigned af[2][4], bf[4][2];
            const int k = kk * 8 + tg;
#pragma unroll
            for (int mt = 0; mt < 2; ++mt) {
                const int m = wm + mt * 16;
                af[mt][0] = As[m + gid][k];
                af[mt][1] = As[m + gid + 8][k];
                af[mt][2] = As[m + gid][k + 4];
                af[mt][3] = As[m + gid + 8][k + 4];
            }
#pragma unroll
            for (int nt = 0; nt < 4; ++nt) {
                const int n = wn + nt * 8 + gid;
                bf[nt][0] = Bs[k][n];
                bf[nt][1] = Bs[k + 4][n];
            }
#pragma unroll
            for (int mt = 0; mt < 2; ++mt)
#pragma unroll
                for (int nt = 0; nt < 4; ++nt)
                    asm volatile(
                        "mma.sync.aligned.m16n8k8.row.col.f32.tf32.tf32.f32 "
                        "{%0,%1,%2,%3}, {%4,%5,%6,%7}, {%8,%9}, {%0,%1,%2,%3};\n"
                        : "+f"(c[mt][nt][0]), "+f"(c[mt][nt][1]),
                          "+f"(c[mt][nt][2]), "+f"(c[mt][nt][3])
                        : "r"(af[mt][0]), "r"(af[mt][1]), "r"(af[mt][2]), "r"(af[mt][3]),
                          "r"(bf[nt][0]), "r"(bf[nt][1]));
        }
    };

    gload(0);
    sstore();
    __syncthreads();
    for (int it = 0; it < ITER; ++it) {
        const bool more = (it + 1 < ITER);
        if (more) gload(it + 1);
        compute();
        __syncthreads();
        if (more) {
            sstore();
            __syncthreads();
        }
    }

#pragma unroll
    for (int nt = 0; nt < 4; ++nt) {
        const int col = bn + wn + nt * 8 + 2 * tg;
        float bv0 = b0[col];
        float bv1 = b0[col + 1];
        if (NPAIR == 2) { bv0 += b1[col]; bv1 += b1[col + 1]; }
#pragma unroll
        for (int mt = 0; mt < 2; ++mt) {
            const int row = bm + wm + mt * 16 + gid;
            float v0 = c[mt][nt][0] + bv0;
            float v1 = c[mt][nt][1] + bv1;
            float v2 = c[mt][nt][2] + bv0;
            float v3 = c[mt][nt][3] + bv1;
            if (ACT == 1) {
                v0 = fmaxf(v0, 0.0f); v1 = fmaxf(v1, 0.0f);
                v2 = fmaxf(v2, 0.0f); v3 = fmaxf(v3, 0.0f);
            }
            C[(long)row * N + col]           = v0;
            C[(long)row * N + col + 1]       = v1;
            C[(long)(row + 8) * N + col]     = v2;
            C[(long)(row + 8) * N + col + 1] = v3;
        }
    }
}

// ---------------- attention scores + softmax -> weights ----------------
__global__ __launch_bounds__(512)
void attn_score_kernel(const float* __restrict__ p_feats,  // B x N x ATTHD
                       const float* __restrict__ atth,     // B x ATTHD
                       const float* __restrict__ Wa,       // ATTHD
                       const float* __restrict__ ba,       // scalar
                       const void*  __restrict__ mask,     // B x (RR+1), col 1+n; may be null
                       int N,
                       float* __restrict__ wout)           // B x 224
{
    const int b = blockIdx.x;
    const int tid = threadIdx.x;
    const int lane = tid & 31, warp = tid >> 5;

    __shared__ float sh_h[ATTHD];
    __shared__ float sh_w[ATTHD];
    __shared__ float sc[224];
    __shared__ float red[16];

    sh_h[tid] = atth[(long)b * ATTHD + tid];
    sh_w[tid] = Wa[tid];
    __syncthreads();

    const float bav = ba[0];

    for (int l = warp; l < N; l += 16) {
        const float* row = p_feats + ((long)b * N + l) * ATTHD;
        float part = 0.0f;
#pragma unroll
        for (int j = 0; j < 16; ++j) {
            int k = lane + 32 * j;
            part += tanhf(row[k] + sh_h[k]) * sh_w[k];
        }
#pragma unroll
        for (int o = 16; o; o >>= 1) part += __shfl_xor_sync(0xffffffffu, part, o);
        if (lane == 0) {
            float s = part + bav;
            if (mask != nullptr && mask_at(mask, (long)b * (RR + 1) + 1 + l)) s = MINV;
            sc[l] = s;
        }
    }
    __syncthreads();

    float v = (tid < N) ? sc[tid] : -3.0e38f;
    float m = v;
#pragma unroll
    for (int o = 16; o; o >>= 1) m = fmaxf(m, __shfl_xor_sync(0xffffffffu, m, o));
    if (lane == 0) red[warp] = m;
    __syncthreads();
    if (warp == 0) {
        float t = (lane < 16) ? red[lane] : -3.0e38f;
#pragma unroll
        for (int o = 16; o; o >>= 1) t = fmaxf(t, __shfl_xor_sync(0xffffffffu, t, o));
        if (lane == 0) red[0] = t;
    }
    __syncthreads();
    const float smax = red[0];
    __syncthreads();

    float e = (tid < N) ? expf(v - smax) : 0.0f;
    float ssum = e;
#pragma unroll
    for (int o = 16; o; o >>= 1) ssum += __shfl_xor_sync(0xffffffffu, ssum, o);
    if (lane == 0) red[warp] = ssum;
    __syncthreads();
    if (warp == 0) {
        float t = (lane < 16) ? red[lane] : 0.0f;
#pragma unroll
        for (int o = 16; o; o >>= 1) t += __shfl_xor_sync(0xffffffffu, t, o);
        if (lane == 0) red[0] = t;
    }
    __syncthreads();
    const float inv = 1.0f / red[0];
    if (tid < N) wout[(long)b * 224 + tid] = e * inv;
}

// ---------------- attention weighted sum ----------------
// grid (B, 2): each block does a 512-dim chunk of RNN. 256 threads, float2 each.
__global__ __launch_bounds__(256)
void attn_wsum_kernel(const float* __restrict__ feats,   // B x N x RNN
                      const float* __restrict__ w,       // B x 224
                      int N,
                      float* __restrict__ out)           // B x RNN
{
    const int b = blockIdx.x;
    const int chunk = blockIdx.y * 512;
    const int t = threadIdx.x;

    __shared__ float sw[224];
    for (int i = t; i < N; i += 256) sw[i] = w[(long)b * 224 + i];
    __syncthreads();

    const float2* f2 = (const float2*)(feats + (long)b * N * RNN + chunk);
    float ax = 0.0f, ay = 0.0f;
#pragma unroll 4
    for (int l = 0; l < N; ++l) {
        const float wv = sw[l];
        const float2 vv = f2[(long)l * (RNN / 2) + t];
        ax += wv * vv.x;
        ay += wv * vv.y;
    }
    ((float2*)(out + (long)b * RNN + chunk))[t] = make_float2(ax, ay);
}

// ---------------- LSTM elementwise ----------------
__global__ __launch_bounds__(256)
void lstm_kernel(const float* __restrict__ sums, const float* __restrict__ a2c,
                 const float* __restrict__ cprev,
                 float* __restrict__ outp, float* __restrict__ outh,
                 float* __restrict__ outc, float* __restrict__ fb) {
    int i = blockIdx.x * blockDim.x + threadIdx.x;
    if (i >= BB * RNN) return;
    int b = i >> 10, d = i & 1023;
    const float* s = sums + (long)b * NSUM;
    float ig = 1.0f / (1.0f + expf(-s[d]));
    float fg = 1.0f / (1.0f + expf(-s[RNN + d]));
    float og = 1.0f / (1.0f + expf(-s[2 * RNN + d]));
    float sg = 1.0f / (1.0f + expf(-s[3 * RNN + d]));
    float t1 = s[4 * RNN + d] + a2c[(long)b * 2 * RNN + d];
    float t2 = s[5 * RNN + d] + a2c[(long)b * 2 * RNN + RNN + d];
    float intr = fmaxf(t1, t2);
    float c = fg * cprev[i] + ig * intr;
    float tc = tanhf(c);
    float h = og * tc;
    outp[i] = h;
    outh[i] = h;
    outc[i] = c;
    fb[i] = sg * tc;
}

// ---------------- det_prob ----------------
__global__ __launch_bounds__(512)
void det_kernel(const float* __restrict__ fre, const float* __restrict__ hoe,
                const float* __restrict__ p_pool, const float* __restrict__ Wp,
                const float* __restrict__ bp, const void* __restrict__ pnt,
                float* __restrict__ det) {
    const int b = blockIdx.x;
    const int tid = threadIdx.x;
    const int lane = tid & 31, warp = tid >> 5;
    __shared__ float sh_h[ATTHD], sh_w[ATTHD], sh_f[ATTHD];
    sh_h[tid] = hoe[(long)b * ATTHD + tid];
    sh_w[tid] = Wp[tid];
    sh_f[tid] = fre[(long)b * ATTHD + tid];
    __syncthreads();
    const float bpv = bp[0];
    for (int n = warp; n < RR + 1; n += 16) {
        float part = 0.0f;
        if (n == 0) {
#pragma unroll
            for (int j = 0; j < 16; ++j) {
                int k = lane + 32 * j;
                part += tanhf(sh_f[k] + sh_h[k]) * sh_w[k];
            }
        } else {
            const float* row = p_pool + ((long)b * RR + (n - 1)) * ATTHD;
#pragma unroll
            for (int j = 0; j < 16; ++j) {
                int k = lane + 32 * j;
                part += tanhf(row[k] + sh_h[k]) * sh_w[k];
            }
        }
#pragma unroll
        for (int o = 16; o; o >>= 1) part += __shfl_xor_sync(0xffffffffu, part, o);
        if (lane == 0) {
            float s = part + bpv;
            if (mask_at(pnt, (long)b * (RR + 1) + n)) s = MINV;
            det[(long)b * (RR + 1) + n] = s;
        }
    }
}

// ---------------- host launch ----------------
extern "C" void kernel_launch(void* const* d_in, const int* in_sizes, int n_in,
                              void* d_out, int out_size) {
    const float* xt        = (const float*)d_in[0];
    const float* att_feats = (const float*)d_in[2];
    const float* p_att     = (const float*)d_in[3];
    const float* pool_f    = (const float*)d_in[4];
    const float* p_pool    = (const float*)d_in[5];
    const void*  att_mask  = d_in[6];
    const void*  pnt_mask  = d_in[7];
    const float* h_prev    = (const float*)d_in[8];
    const float* c_prev    = (const float*)d_in[9];
    const float* W_h2att = (const float*)d_in[10]; const float* b_h2att = (const float*)d_in[11];
    const float* W_a1    = (const float*)d_in[12]; const float* b_a1    = (const float*)d_in[13];
    const float* W_h1att = (const float*)d_in[14]; const float* b_h1att = (const float*)d_in[15];
    const float* W_a2    = (const float*)d_in[16]; const float* b_a2    = (const float*)d_in[17];
    const float* W_i2h   = (const float*)d_in[18]; const float* b_i2h   = (const float*)d_in[19];
    const float* W_h2h   = (const float*)d_in[20]; const float* b_h2h   = (const float*)d_in[21];
    const float* W_a2c1  = (const float*)d_in[22]; const float* b_a2c1  = (const float*)d_in[23];
    const float* W_ffc1  = (const float*)d_in[24]; const float* b_ffc1  = (const float*)d_in[25];
    const float* W_ffc2  = (const float*)d_in[26]; const float* b_ffc2  = (const float*)d_in[27];
    const float* W_hfc1  = (const float*)d_in[28]; const float* b_hfc1  = (const float*)d_in[29];
    const float* W_ap    = (const float*)d_in[30]; const float* b_ap    = (const float*)d_in[31];

    float* out = (float*)d_out;
    float* out_output = out;                                   // B*RNN
    float* out_det    = out + (long)BB * RNN;                  // B*(RR+1)
    float* out_h      = out_det + (long)BB * (RR + 1);         // B*RNN
    float* out_c      = out_h + (long)BB * RNN;                // B*RNN

    float *atth1, *atth2, *res1, *res2, *sums, *a2c, *fakebox, *fakereg, *fre, *hoe, *w1, *w2;
    cudaGetSymbolAddress((void**)&atth1,   g_atth1);
    cudaGetSymbolAddress((void**)&atth2,   g_atth2);
    cudaGetSymbolAddress((void**)&res1,    g_res1);
    cudaGetSymbolAddress((void**)&res2,    g_res2);
    cudaGetSymbolAddress((void**)&sums,    g_sums);
    cudaGetSymbolAddress((void**)&a2c,     g_a2c);
    cudaGetSymbolAddress((void**)&fakebox, g_fakebox);
    cudaGetSymbolAddress((void**)&fakereg, g_fakereg);
    cudaGetSymbolAddress((void**)&fre,     g_fre);
    cudaGetSymbolAddress((void**)&hoe,     g_hoe);
    cudaGetSymbolAddress((void**)&w1,      g_w1);
    cudaGetSymbolAddress((void**)&w2,      g_w2);

    dim3 blk(128);

    // 0. mask dtype detection
    detect_mask_kernel<<<1, 256>>>((const unsigned int*)att_mask, BB * (RR + 1) / 4);

    // 1. atth1 = h @ W_h2att + b ; atth2 = h @ W_h1att + b  (one launch, z=2)
    mma_gemm<1, 0><<<dim3(ATTHD / 64, BB / 64, 2), blk>>>(
        h_prev, W_h2att, nullptr, nullptr, b_h2att, nullptr, atth1,
        h_prev, W_h1att, b_h1att, atth2, BB, ATTHD);

    // 2. attention scores + softmax
    attn_score_kernel<<<BB, 512>>>(p_att, atth1, W_a1, b_a1, nullptr, LL, w1);
    attn_score_kernel<<<BB, 512>>>(p_pool, atth2, W_a2, b_a2, att_mask, RR, w2);

    // 3. sums = xt @ W_i2h + h @ W_h2h + biases
    mma_gemm<2, 0><<<dim3(NSUM / 64, BB / 64, 1), blk>>>(
        xt, W_i2h, h_prev, W_h2h, b_i2h, b_h2h, sums,
        nullptr, nullptr, nullptr, nullptr, BB, NSUM);

    // 4. weighted sums
    attn_wsum_kernel<<<dim3(BB, 2), 256>>>(att_feats, w1, LL, res1);
    attn_wsum_kernel<<<dim3(BB, 2), 256>>>(pool_f, w2, RR, res2);

    // 5. a2c = (res1 + res2) @ W_a2c1 + 2*b_a2c1
    mma_gemm<2, 0><<<dim3(2 * RNN / 64, BB / 64, 1), blk>>>(
        res1, W_a2c1, res2, W_a2c1, b_a2c1, b_a2c1, a2c,
        nullptr, nullptr, nullptr, nullptr, BB, 2 * RNN);

    // 6. LSTM elementwise -> output, next_h, next_c, fake_box
    lstm_kernel<<<(BB * RNN + 255) / 256, 256>>>(sums, a2c, c_prev,
                                                 out_output, out_h, out_c, fakebox);

    // 7. fake_region = relu(fake_box @ W_ffc1 + b)
    mma_gemm<1, 1><<<dim3(RNN / 64, BB / 64, 1), blk>>>(
        fakebox, W_ffc1, nullptr, nullptr, b_ffc1, nullptr, fakereg,
        nullptr, nullptr, nullptr, nullptr, BB, RNN);

    // 8. fre = fake_region @ W_ffc2 + b ; hoe = next_h @ W_hfc1 + b  (z=2)
    mma_gemm<1, 0><<<dim3(ATTHD / 64, BB / 64, 2), blk>>>(
        fakereg, W_ffc2, nullptr, nullptr, b_ffc2, nullptr, fre,
        out_h, W_hfc1, b_hfc1, hoe, BB, ATTHD);

    // 9. det_prob
    det_kernel<<<BB, 512>>>(fre, hoe, p_pool, W_ap, b_ap, pnt_mask, out_det);

    (void)in_sizes; (void)n_in; (void)out_size;
}